// round 3
// baseline (speedup 1.0000x reference)
#include <cuda_runtime.h>

#define NN   100000
#define DD   64
#define NG   1024
#define NL   4
#define OUTD 16

// Scratch (static __device__ arrays per harness rules)
__device__ float g_bufA[NN * DD];
__device__ float g_bufB[NN * DD];
__device__ float g_agg[NN * DD];
__device__ float g_pool[NG * DD];

typedef unsigned long long u64;

__device__ __forceinline__ u64 pack2(float x) {
    u64 r;
    asm("mov.b64 %0, {%1, %1};" : "=l"(r) : "f"(x));
    return r;
}
__device__ __forceinline__ void fma2(u64 &d, u64 a, u64 b) {
    asm("fma.rn.f32x2 %0, %1, %2, %0;" : "+l"(d) : "l"(a), "l"(b));
}
__device__ __forceinline__ void unpack2(u64 v, float &lo, float &hi) {
    asm("mov.b64 {%0, %1}, %2;" : "=f"(lo), "=f"(hi) : "l"(v));
}

__global__ void zero_kernel(float4 *p, int n4) {
    int i = blockIdx.x * blockDim.x + threadIdx.x;
    if (i < n4) p[i] = make_float4(0.f, 0.f, 0.f, 0.f);
}

// One edge handled by 16 threads, each does one float4 gather + one v4 reduction.
__global__ void scatter_kernel(const float4 *__restrict__ h4,
                               const int *__restrict__ src,
                               const int *__restrict__ dst,
                               float *__restrict__ agg, int nE) {
    int t = blockIdx.x * blockDim.x + threadIdx.x;
    int e = t >> 4;
    if (e >= nE) return;
    int s = t & 15;
    int si = src[e];
    int di = dst[e];
    float4 v = h4[si * 16 + s];
    float *p = agg + (size_t)di * 64 + s * 4;
    asm volatile("red.global.add.v4.f32 [%0], {%1, %2, %3, %4};"
                 :: "l"(p), "f"(v.x), "f"(v.y), "f"(v.z), "f"(v.w)
                 : "memory");
}

// Fused: out = relu(agg @ Wrel + brel + h @ Wroot), one row per thread,
// f32x2 packed FMAs, weights broadcast from SMEM.
__global__ void __launch_bounds__(128) layer_kernel(
    const float4 *__restrict__ A4, const float4 *__restrict__ H4,
    const float *__restrict__ Wrel, const float *__restrict__ Wroot,
    const float *__restrict__ brel, float4 *__restrict__ Out4, int nRows) {
    __shared__ __align__(16) float sWr[DD * DD];
    __shared__ __align__(16) float sWo[DD * DD];
    __shared__ __align__(16) float sB[DD];

    int tid = threadIdx.x;
    for (int i = tid; i < DD * DD / 4; i += 128) {
        ((float4 *)sWr)[i] = ((const float4 *)Wrel)[i];
        ((float4 *)sWo)[i] = ((const float4 *)Wroot)[i];
    }
    if (tid < DD / 4) ((float4 *)sB)[tid] = ((const float4 *)brel)[tid];
    __syncthreads();

    int row = blockIdx.x * 128 + tid;
    if (row >= nRows) return;

    u64 acc[32];
    const u64 *b2 = (const u64 *)sB;
#pragma unroll
    for (int c = 0; c < 32; c++) acc[c] = b2[c];

#pragma unroll 1
    for (int kk = 0; kk < 16; kk++) {
        float4 av = A4[(size_t)row * 16 + kk];
        float4 hv = H4[(size_t)row * 16 + kk];
#pragma unroll
        for (int j = 0; j < 4; j++) {
            int k = kk * 4 + j;
            float af = (&av.x)[j];
            float hf = (&hv.x)[j];
            u64 a2 = pack2(af);
            u64 h2 = pack2(hf);
            const ulonglong2 *wr = (const ulonglong2 *)(sWr + k * DD);
            const ulonglong2 *wo = (const ulonglong2 *)(sWo + k * DD);
#pragma unroll
            for (int c = 0; c < 16; c++) {
                ulonglong2 w1v = wr[c];
                fma2(acc[2 * c], a2, w1v.x);
                fma2(acc[2 * c + 1], a2, w1v.y);
                ulonglong2 w2v = wo[c];
                fma2(acc[2 * c], h2, w2v.x);
                fma2(acc[2 * c + 1], h2, w2v.y);
            }
        }
    }

#pragma unroll
    for (int c = 0; c < 16; c++) {
        float4 o;
        float lo, hi;
        unpack2(acc[2 * c], lo, hi);
        o.x = fmaxf(lo, 0.f);
        o.y = fmaxf(hi, 0.f);
        unpack2(acc[2 * c + 1], lo, hi);
        o.z = fmaxf(lo, 0.f);
        o.w = fmaxf(hi, 0.f);
        Out4[(size_t)row * 16 + c] = o;
    }
}

// Global add-pool: node rows reduced into per-graph rows (batch-indexed).
__global__ void pool_kernel(const float4 *__restrict__ h4,
                            const int *__restrict__ batch,
                            float *__restrict__ pool, int nNodes) {
    int t = blockIdx.x * blockDim.x + threadIdx.x;
    int n = t >> 4;
    if (n >= nNodes) return;
    int s = t & 15;
    int g = batch[n];
    float4 v = h4[(size_t)n * 16 + s];
    float *p = pool + g * 64 + s * 4;
    asm volatile("red.global.add.v4.f32 [%0], {%1, %2, %3, %4};"
                 :: "l"(p), "f"(v.x), "f"(v.y), "f"(v.z), "f"(v.w)
                 : "memory");
}

// y = relu(pool @ W1 + b1) @ W2 + b2 ; one warp per graph, 4 graphs per block.
__global__ void head_kernel(const float *__restrict__ pool,
                            const float *__restrict__ W1,
                            const float *__restrict__ b1,
                            const float *__restrict__ W2,
                            const float *__restrict__ b2,
                            float *__restrict__ out) {
    __shared__ float st[4][DD];
    int w = threadIdx.x >> 5;
    int lane = threadIdx.x & 31;
    int g = blockIdx.x * 4 + w;

    float acc0 = b1[lane];
    float acc1 = b1[lane + 32];
#pragma unroll 4
    for (int k = 0; k < DD; k++) {
        float pv = pool[g * DD + k];
        acc0 += pv * W1[k * DD + lane];
        acc1 += pv * W1[k * DD + lane + 32];
    }
    st[w][lane] = fmaxf(acc0, 0.f);
    st[w][lane + 32] = fmaxf(acc1, 0.f);
    __syncwarp();

    if (lane < OUTD) {
        float acc = b2[lane];
#pragma unroll 4
        for (int k = 0; k < DD; k++) acc += st[w][k] * W2[k * OUTD + lane];
        out[g * OUTD + lane] = acc;
    }
}

extern "C" void kernel_launch(void *const *d_in, const int *in_sizes, int n_in,
                              void *d_out, int out_size) {
    const float *x     = (const float *)d_in[0];
    const int   *ei    = (const int *)d_in[1];
    const int   *batch = (const int *)d_in[2];
    const float *Wrel  = (const float *)d_in[3];
    const float *brel  = (const float *)d_in[4];
    const float *Wroot = (const float *)d_in[5];
    const float *W1    = (const float *)d_in[6];
    const float *b1    = (const float *)d_in[7];
    const float *W2    = (const float *)d_in[8];
    const float *b2    = (const float *)d_in[9];

    int nE = in_sizes[1] / 2;
    int nN = in_sizes[0] / DD;
    const int *src = ei;
    const int *dst = ei + nE;

    float *bufA, *bufB, *agg, *pool;
    cudaGetSymbolAddress((void **)&bufA, g_bufA);
    cudaGetSymbolAddress((void **)&bufB, g_bufB);
    cudaGetSymbolAddress((void **)&agg, g_agg);
    cudaGetSymbolAddress((void **)&pool, g_pool);

    const float *hcur = x;
    float *houts[NL] = {bufA, bufB, bufA, bufB};

    int aggN4 = nN * 16;
    int scatterThreads = nE * 16;

    for (int l = 0; l < NL; l++) {
        zero_kernel<<<(aggN4 + 255) / 256, 256>>>((float4 *)agg, aggN4);
        scatter_kernel<<<(scatterThreads + 255) / 256, 256>>>(
            (const float4 *)hcur, src, dst, agg, nE);
        layer_kernel<<<(nN + 127) / 128, 128>>>(
            (const float4 *)agg, (const float4 *)hcur,
            Wrel + (size_t)l * DD * DD, Wroot + (size_t)l * DD * DD,
            brel + (size_t)l * DD, (float4 *)houts[l], nN);
        hcur = houts[l];
    }

    int poolN4 = NG * 16;
    zero_kernel<<<(poolN4 + 255) / 256, 256>>>((float4 *)pool, poolN4);
    pool_kernel<<<(nN * 16 + 255) / 256, 256>>>(
        (const float4 *)hcur, batch, pool, nN);
    head_kernel<<<NG / 4, 128>>>(pool, W1, b1, W2, b2, (float *)d_out);
}

// round 4
// speedup vs baseline: 1.2706x; 1.2706x over previous
#include <cuda_runtime.h>

#define NN   100000
#define NEMAX 1000000
#define DD   64
#define NG   1024
#define NL   4
#define OUTD 16
#define SCAN_B 512
#define NBLK_MAX 256   // ceil(100000/512)=196

// Scratch (static __device__ arrays per harness rules)
__device__ float g_bufA[NN * DD];
__device__ float g_bufB[NN * DD];
__device__ float g_agg[NN * DD];
__device__ float g_pool[NG * DD];
__device__ int   g_rowStart[NN + 1];
__device__ int   g_cursor[NN];
__device__ int   g_bsum[NBLK_MAX];
__device__ int   g_csrSrc[NEMAX];

typedef unsigned long long u64;

__device__ __forceinline__ u64 pack2(float x) {
    u64 r;
    asm("mov.b64 %0, {%1, %1};" : "=l"(r) : "f"(x));
    return r;
}
__device__ __forceinline__ void fma2(u64 &d, u64 a, u64 b) {
    asm("fma.rn.f32x2 %0, %1, %2, %0;" : "+l"(d) : "l"(a), "l"(b));
}
__device__ __forceinline__ void unpack2(u64 v, float &lo, float &hi) {
    asm("mov.b64 {%0, %1}, %2;" : "=f"(lo), "=f"(hi) : "l"(v));
}

__global__ void zero_kernel(float4 *p, int n4) {
    int i = blockIdx.x * blockDim.x + threadIdx.x;
    if (i < n4) p[i] = make_float4(0.f, 0.f, 0.f, 0.f);
}

// ---------- CSR build (once per call; edges are layer-invariant) ----------
__global__ void zero_int_kernel(int *p, int n) {
    int i = blockIdx.x * blockDim.x + threadIdx.x;
    if (i < n) p[i] = 0;
}

__global__ void hist_kernel(const int *__restrict__ dst, int *__restrict__ deg,
                            int nE) {
    int i = blockIdx.x * blockDim.x + threadIdx.x;
    if (i < nE) atomicAdd(&deg[dst[i]], 1);
}

// Block-level exclusive scan; writes per-block exclusive values into out,
// block totals into bsum.
__global__ void scan1_kernel(const int *__restrict__ deg, int *__restrict__ out,
                             int *__restrict__ bsum, int n) {
    __shared__ int sh[SCAN_B];
    int i = blockIdx.x * SCAN_B + threadIdx.x;
    int v = (i < n) ? deg[i] : 0;
    sh[threadIdx.x] = v;
    __syncthreads();
    for (int off = 1; off < SCAN_B; off <<= 1) {
        int t = (threadIdx.x >= off) ? sh[threadIdx.x - off] : 0;
        __syncthreads();
        sh[threadIdx.x] += t;
        __syncthreads();
    }
    if (i < n) out[i] = sh[threadIdx.x] - v;  // exclusive
    if (threadIdx.x == SCAN_B - 1) bsum[blockIdx.x] = sh[threadIdx.x];
}

// Single-block exclusive scan of block totals (nb <= 256).
__global__ void scan2_kernel(int *__restrict__ bsum, int nb) {
    __shared__ int sh[256];
    int v = (threadIdx.x < nb) ? bsum[threadIdx.x] : 0;
    sh[threadIdx.x] = v;
    __syncthreads();
    for (int off = 1; off < 256; off <<= 1) {
        int t = (threadIdx.x >= off) ? sh[threadIdx.x - off] : 0;
        __syncthreads();
        sh[threadIdx.x] += t;
        __syncthreads();
    }
    if (threadIdx.x < nb) bsum[threadIdx.x] = sh[threadIdx.x] - v;
}

__global__ void scan3_kernel(int *__restrict__ rowStart,
                             const int *__restrict__ bsum,
                             int *__restrict__ cursor, int n, int nE) {
    int i = blockIdx.x * blockDim.x + threadIdx.x;
    if (i < n) {
        int rs = rowStart[i] + bsum[i / SCAN_B];
        rowStart[i] = rs;
        cursor[i] = rs;
    }
    if (i == 0) rowStart[n] = nE;
}

__global__ void fill_kernel(const int *__restrict__ src,
                            const int *__restrict__ dst,
                            int *__restrict__ cursor,
                            int *__restrict__ csrSrc, int nE) {
    int i = blockIdx.x * blockDim.x + threadIdx.x;
    if (i < nE) {
        int pos = atomicAdd(&cursor[dst[i]], 1);
        csrSrc[pos] = src[i];
    }
}

// ---------- Per-layer gather aggregation: agg[n] = sum_{j in N(n)} h[j] ----
// 16 threads per node; thread s owns float4 chunk s of the 64-float row.
__global__ void gather_kernel(const float4 *__restrict__ h4,
                              const int *__restrict__ rowStart,
                              const int *__restrict__ csrSrc,
                              float4 *__restrict__ agg4, int nNodes) {
    int t = blockIdx.x * blockDim.x + threadIdx.x;
    int n = t >> 4;
    if (n >= nNodes) return;
    int s = t & 15;
    int beg = rowStart[n];
    int end = rowStart[n + 1];
    float4 acc = make_float4(0.f, 0.f, 0.f, 0.f);
    for (int j = beg; j < end; j++) {
        int si = __ldg(&csrSrc[j]);
        float4 v = h4[(size_t)si * 16 + s];
        acc.x += v.x; acc.y += v.y; acc.z += v.z; acc.w += v.w;
    }
    agg4[(size_t)n * 16 + s] = acc;
}

// Fused: out = relu(agg @ Wrel + brel + h @ Wroot), one row per thread,
// f32x2 packed FMAs, weights broadcast from SMEM.
__global__ void __launch_bounds__(128) layer_kernel(
    const float4 *__restrict__ A4, const float4 *__restrict__ H4,
    const float *__restrict__ Wrel, const float *__restrict__ Wroot,
    const float *__restrict__ brel, float4 *__restrict__ Out4, int nRows) {
    __shared__ __align__(16) float sWr[DD * DD];
    __shared__ __align__(16) float sWo[DD * DD];
    __shared__ __align__(16) float sB[DD];

    int tid = threadIdx.x;
    for (int i = tid; i < DD * DD / 4; i += 128) {
        ((float4 *)sWr)[i] = ((const float4 *)Wrel)[i];
        ((float4 *)sWo)[i] = ((const float4 *)Wroot)[i];
    }
    if (tid < DD / 4) ((float4 *)sB)[tid] = ((const float4 *)brel)[tid];
    __syncthreads();

    int row = blockIdx.x * 128 + tid;
    if (row >= nRows) return;

    u64 acc[32];
    const u64 *b2 = (const u64 *)sB;
#pragma unroll
    for (int c = 0; c < 32; c++) acc[c] = b2[c];

#pragma unroll 1
    for (int kk = 0; kk < 16; kk++) {
        float4 av = A4[(size_t)row * 16 + kk];
        float4 hv = H4[(size_t)row * 16 + kk];
#pragma unroll
        for (int j = 0; j < 4; j++) {
            int k = kk * 4 + j;
            float af = (&av.x)[j];
            float hf = (&hv.x)[j];
            u64 a2 = pack2(af);
            u64 h2 = pack2(hf);
            const ulonglong2 *wr = (const ulonglong2 *)(sWr + k * DD);
            const ulonglong2 *wo = (const ulonglong2 *)(sWo + k * DD);
#pragma unroll
            for (int c = 0; c < 16; c++) {
                ulonglong2 w1v = wr[c];
                fma2(acc[2 * c], a2, w1v.x);
                fma2(acc[2 * c + 1], a2, w1v.y);
                ulonglong2 w2v = wo[c];
                fma2(acc[2 * c], h2, w2v.x);
                fma2(acc[2 * c + 1], h2, w2v.y);
            }
        }
    }

#pragma unroll
    for (int c = 0; c < 16; c++) {
        float4 o;
        float lo, hi;
        unpack2(acc[2 * c], lo, hi);
        o.x = fmaxf(lo, 0.f);
        o.y = fmaxf(hi, 0.f);
        unpack2(acc[2 * c + 1], lo, hi);
        o.z = fmaxf(lo, 0.f);
        o.w = fmaxf(hi, 0.f);
        Out4[(size_t)row * 16 + c] = o;
    }
}

// Global add-pool: node rows reduced into per-graph rows (batch-indexed).
__global__ void pool_kernel(const float4 *__restrict__ h4,
                            const int *__restrict__ batch,
                            float *__restrict__ pool, int nNodes) {
    int t = blockIdx.x * blockDim.x + threadIdx.x;
    int n = t >> 4;
    if (n >= nNodes) return;
    int s = t & 15;
    int g = batch[n];
    float4 v = h4[(size_t)n * 16 + s];
    float *p = pool + g * 64 + s * 4;
    asm volatile("red.global.add.v4.f32 [%0], {%1, %2, %3, %4};"
                 :: "l"(p), "f"(v.x), "f"(v.y), "f"(v.z), "f"(v.w)
                 : "memory");
}

// y = relu(pool @ W1 + b1) @ W2 + b2 ; one warp per graph, 4 graphs per block.
__global__ void head_kernel(const float *__restrict__ pool,
                            const float *__restrict__ W1,
                            const float *__restrict__ b1,
                            const float *__restrict__ W2,
                            const float *__restrict__ b2,
                            float *__restrict__ out) {
    __shared__ float st[4][DD];
    int w = threadIdx.x >> 5;
    int lane = threadIdx.x & 31;
    int g = blockIdx.x * 4 + w;

    float acc0 = b1[lane];
    float acc1 = b1[lane + 32];
#pragma unroll 4
    for (int k = 0; k < DD; k++) {
        float pv = pool[g * DD + k];
        acc0 += pv * W1[k * DD + lane];
        acc1 += pv * W1[k * DD + lane + 32];
    }
    st[w][lane] = fmaxf(acc0, 0.f);
    st[w][lane + 32] = fmaxf(acc1, 0.f);
    __syncwarp();

    if (lane < OUTD) {
        float acc = b2[lane];
#pragma unroll 4
        for (int k = 0; k < DD; k++) acc += st[w][k] * W2[k * OUTD + lane];
        out[g * OUTD + lane] = acc;
    }
}

extern "C" void kernel_launch(void *const *d_in, const int *in_sizes, int n_in,
                              void *d_out, int out_size) {
    const float *x     = (const float *)d_in[0];
    const int   *ei    = (const int *)d_in[1];
    const int   *batch = (const int *)d_in[2];
    const float *Wrel  = (const float *)d_in[3];
    const float *brel  = (const float *)d_in[4];
    const float *Wroot = (const float *)d_in[5];
    const float *W1    = (const float *)d_in[6];
    const float *b1    = (const float *)d_in[7];
    const float *W2    = (const float *)d_in[8];
    const float *b2    = (const float *)d_in[9];

    int nE = in_sizes[1] / 2;
    int nN = in_sizes[0] / DD;
    const int *src = ei;
    const int *dst = ei + nE;

    float *bufA, *bufB, *agg, *pool;
    int *rowStart, *cursor, *bsum, *csrSrc;
    cudaGetSymbolAddress((void **)&bufA, g_bufA);
    cudaGetSymbolAddress((void **)&bufB, g_bufB);
    cudaGetSymbolAddress((void **)&agg, g_agg);
    cudaGetSymbolAddress((void **)&pool, g_pool);
    cudaGetSymbolAddress((void **)&rowStart, g_rowStart);
    cudaGetSymbolAddress((void **)&cursor, g_cursor);
    cudaGetSymbolAddress((void **)&bsum, g_bsum);
    cudaGetSymbolAddress((void **)&csrSrc, g_csrSrc);

    // ---- CSR build (dst -> srcs), once per call ----
    int nb = (nN + SCAN_B - 1) / SCAN_B;
    zero_int_kernel<<<(nN + 511) / 512, 512>>>(rowStart, nN);  // use rowStart as deg
    hist_kernel<<<(nE + 511) / 512, 512>>>(dst, rowStart, nE);
    scan1_kernel<<<nb, SCAN_B>>>(rowStart, rowStart, bsum, nN);
    scan2_kernel<<<1, 256>>>(bsum, nb);
    scan3_kernel<<<(nN + 511) / 512, 512>>>(rowStart, bsum, cursor, nN, nE);
    fill_kernel<<<(nE + 511) / 512, 512>>>(src, dst, cursor, csrSrc, nE);

    const float *hcur = x;
    float *houts[NL] = {bufA, bufB, bufA, bufB};

    int gatherThreads = nN * 16;
    for (int l = 0; l < NL; l++) {
        gather_kernel<<<(gatherThreads + 255) / 256, 256>>>(
            (const float4 *)hcur, rowStart, csrSrc, (float4 *)agg, nN);
        layer_kernel<<<(nN + 127) / 128, 128>>>(
            (const float4 *)agg, (const float4 *)hcur,
            Wrel + (size_t)l * DD * DD, Wroot + (size_t)l * DD * DD,
            brel + (size_t)l * DD, (float4 *)houts[l], nN);
        hcur = houts[l];
    }

    int poolN4 = NG * 16;
    zero_kernel<<<(poolN4 + 255) / 256, 256>>>((float4 *)pool, poolN4);
    pool_kernel<<<(nN * 16 + 255) / 256, 256>>>(
        (const float4 *)hcur, batch, pool, nN);
    head_kernel<<<NG / 4, 128>>>(pool, W1, b1, W2, b2, (float *)d_out);
}

// round 11
// speedup vs baseline: 1.4314x; 1.1265x over previous
#include <cuda_runtime.h>

#define NN   100000
#define NEMAX 1000000
#define DD   64
#define NG   1024
#define NL   4
#define OUTD 16
#define SCAN_B 512
#define NBLK_MAX 256

// Scratch (static __device__ arrays per harness rules)
__device__ float g_bufA[NN * DD];
__device__ float g_bufB[NN * DD];
__device__ float g_agg[NN * DD];
__device__ float g_pool[NG * DD];
__device__ int   g_rowStart[NN + 1];
__device__ int   g_cursor[NN];
__device__ int   g_bsum[NBLK_MAX];
__device__ int   g_csrSrc[NEMAX];

typedef unsigned long long u64;

__device__ __forceinline__ u64 pack2(float x) {
    u64 r;
    asm("mov.b64 %0, {%1, %1};" : "=l"(r) : "f"(x));
    return r;
}
__device__ __forceinline__ void fma2(u64 &d, u64 a, u64 b) {
    asm("fma.rn.f32x2 %0, %1, %2, %0;" : "+l"(d) : "l"(a), "l"(b));
}
__device__ __forceinline__ void unpack2(u64 v, float &lo, float &hi) {
    asm("mov.b64 {%0, %1}, %2;" : "=f"(lo), "=f"(hi) : "l"(v));
}

__global__ void zero_kernel(float4 *p, int n4) {
    int i = blockIdx.x * blockDim.x + threadIdx.x;
    if (i < n4) p[i] = make_float4(0.f, 0.f, 0.f, 0.f);
}

// ---------- CSR build (once per call; edges are layer-invariant) ----------
__global__ void zero_int_kernel(int *p, int n) {
    int i = blockIdx.x * blockDim.x + threadIdx.x;
    if (i < n) p[i] = 0;
}

__global__ void hist_kernel(const int *__restrict__ dst, int *__restrict__ deg,
                            int nE) {
    int i = blockIdx.x * blockDim.x + threadIdx.x;
    if (i < nE) atomicAdd(&deg[dst[i]], 1);
}

__global__ void scan1_kernel(const int *__restrict__ deg, int *__restrict__ out,
                             int *__restrict__ bsum, int n) {
    __shared__ int sh[SCAN_B];
    int i = blockIdx.x * SCAN_B + threadIdx.x;
    int v = (i < n) ? deg[i] : 0;
    sh[threadIdx.x] = v;
    __syncthreads();
    for (int off = 1; off < SCAN_B; off <<= 1) {
        int t = (threadIdx.x >= off) ? sh[threadIdx.x - off] : 0;
        __syncthreads();
        sh[threadIdx.x] += t;
        __syncthreads();
    }
    if (i < n) out[i] = sh[threadIdx.x] - v;  // exclusive
    if (threadIdx.x == SCAN_B - 1) bsum[blockIdx.x] = sh[threadIdx.x];
}

__global__ void scan2_kernel(int *__restrict__ bsum, int nb) {
    __shared__ int sh[256];
    int v = (threadIdx.x < nb) ? bsum[threadIdx.x] : 0;
    sh[threadIdx.x] = v;
    __syncthreads();
    for (int off = 1; off < 256; off <<= 1) {
        int t = (threadIdx.x >= off) ? sh[threadIdx.x - off] : 0;
        __syncthreads();
        sh[threadIdx.x] += t;
        __syncthreads();
    }
    if (threadIdx.x < nb) bsum[threadIdx.x] = sh[threadIdx.x] - v;
}

__global__ void scan3_kernel(int *__restrict__ rowStart,
                             const int *__restrict__ bsum,
                             int *__restrict__ cursor, int n, int nE) {
    int i = blockIdx.x * blockDim.x + threadIdx.x;
    if (i < n) {
        int rs = rowStart[i] + bsum[i / SCAN_B];
        rowStart[i] = rs;
        cursor[i] = rs;
    }
    if (i == 0) rowStart[n] = nE;
}

__global__ void fill_kernel(const int *__restrict__ src,
                            const int *__restrict__ dst,
                            int *__restrict__ cursor,
                            int *__restrict__ csrSrc, int nE) {
    int i = blockIdx.x * blockDim.x + threadIdx.x;
    if (i < nE) {
        int pos = atomicAdd(&cursor[dst[i]], 1);
        csrSrc[pos] = src[i];
    }
}

// ---------- Per-layer gather aggregation: agg[n] = sum_{j in N(n)} h[j] ----
__global__ void gather_kernel(const float4 *__restrict__ h4,
                              const int *__restrict__ rowStart,
                              const int *__restrict__ csrSrc,
                              float4 *__restrict__ agg4, int nNodes) {
    int t = blockIdx.x * blockDim.x + threadIdx.x;
    int n = t >> 4;
    if (n >= nNodes) return;
    int s = t & 15;
    int beg = rowStart[n];
    int end = rowStart[n + 1];
    float4 acc = make_float4(0.f, 0.f, 0.f, 0.f);
    for (int j = beg; j < end; j++) {
        int si = __ldg(&csrSrc[j]);
        float4 v = h4[(size_t)si * 16 + s];
        acc.x += v.x; acc.y += v.y; acc.z += v.z; acc.w += v.w;
    }
    agg4[(size_t)n * 16 + s] = acc;
}

// Fused: out = relu(agg @ Wrel + brel + h @ Wroot).
// 2 rows per thread (256-row tile per CTA) so each weight LDS feeds both rows.
// If isLast: instead of storing h, reduce relu'ed row into pool[batch[row]].
__global__ void __launch_bounds__(128) layer_kernel(
    const float4 *__restrict__ A4, const float4 *__restrict__ H4,
    const float *__restrict__ Wrel, const float *__restrict__ Wroot,
    const float *__restrict__ brel, float4 *__restrict__ Out4,
    const int *__restrict__ batch, float *__restrict__ pool,
    int nRows, int isLast) {
    __shared__ __align__(16) float sWr[DD * DD];
    __shared__ __align__(16) float sWo[DD * DD];
    __shared__ __align__(16) float sB[DD];

    int tid = threadIdx.x;
    for (int i = tid; i < DD * DD / 4; i += 128) {
        ((float4 *)sWr)[i] = ((const float4 *)Wrel)[i];
        ((float4 *)sWo)[i] = ((const float4 *)Wroot)[i];
    }
    if (tid < DD / 4) ((float4 *)sB)[tid] = ((const float4 *)brel)[tid];
    __syncthreads();

    int r0 = blockIdx.x * 256 + tid;
    int r1 = r0 + 128;
    bool v0 = r0 < nRows;
    bool v1 = r1 < nRows;
    if (!v0) return;  // r1 > r0, so nothing to do

    u64 acc0[32], acc1[32];
    const u64 *b2 = (const u64 *)sB;
#pragma unroll
    for (int c = 0; c < 32; c++) { acc0[c] = b2[c]; acc1[c] = b2[c]; }

    const float4 zero4 = make_float4(0.f, 0.f, 0.f, 0.f);

#pragma unroll 1
    for (int kk = 0; kk < 16; kk++) {
        float4 av0 = A4[(size_t)r0 * 16 + kk];
        float4 hv0 = H4[(size_t)r0 * 16 + kk];
        float4 av1 = v1 ? A4[(size_t)r1 * 16 + kk] : zero4;
        float4 hv1 = v1 ? H4[(size_t)r1 * 16 + kk] : zero4;
#pragma unroll
        for (int j = 0; j < 4; j++) {
            int k = kk * 4 + j;
            u64 a20 = pack2((&av0.x)[j]);
            u64 h20 = pack2((&hv0.x)[j]);
            u64 a21 = pack2((&av1.x)[j]);
            u64 h21 = pack2((&hv1.x)[j]);
            const ulonglong2 *wr = (const ulonglong2 *)(sWr + k * DD);
            const ulonglong2 *wo = (const ulonglong2 *)(sWo + k * DD);
#pragma unroll
            for (int c = 0; c < 16; c++) {
                ulonglong2 w1v = wr[c];
                fma2(acc0[2 * c],     a20, w1v.x);
                fma2(acc0[2 * c + 1], a20, w1v.y);
                fma2(acc1[2 * c],     a21, w1v.x);
                fma2(acc1[2 * c + 1], a21, w1v.y);
                ulonglong2 w2v = wo[c];
                fma2(acc0[2 * c],     h20, w2v.x);
                fma2(acc0[2 * c + 1], h20, w2v.y);
                fma2(acc1[2 * c],     h21, w2v.x);
                fma2(acc1[2 * c + 1], h21, w2v.y);
            }
        }
    }

    // epilogue
    if (!isLast) {
#pragma unroll
        for (int c = 0; c < 16; c++) {
            float4 o;
            float lo, hi;
            unpack2(acc0[2 * c], lo, hi);
            o.x = fmaxf(lo, 0.f); o.y = fmaxf(hi, 0.f);
            unpack2(acc0[2 * c + 1], lo, hi);
            o.z = fmaxf(lo, 0.f); o.w = fmaxf(hi, 0.f);
            Out4[(size_t)r0 * 16 + c] = o;
        }
        if (v1) {
#pragma unroll
            for (int c = 0; c < 16; c++) {
                float4 o;
                float lo, hi;
                unpack2(acc1[2 * c], lo, hi);
                o.x = fmaxf(lo, 0.f); o.y = fmaxf(hi, 0.f);
                unpack2(acc1[2 * c + 1], lo, hi);
                o.z = fmaxf(lo, 0.f); o.w = fmaxf(hi, 0.f);
                Out4[(size_t)r1 * 16 + c] = o;
            }
        }
    } else {
        // fused global_add_pool: relu'ed row -> pool[batch[row]]
        int g0 = batch[r0];
        float *p0 = pool + (size_t)g0 * DD;
#pragma unroll
        for (int c = 0; c < 16; c++) {
            float lo, hi, z, w;
            unpack2(acc0[2 * c], lo, hi);
            unpack2(acc0[2 * c + 1], z, w);
            lo = fmaxf(lo, 0.f); hi = fmaxf(hi, 0.f);
            z = fmaxf(z, 0.f);  w = fmaxf(w, 0.f);
            asm volatile("red.global.add.v4.f32 [%0], {%1, %2, %3, %4};"
                         :: "l"(p0 + c * 4), "f"(lo), "f"(hi), "f"(z), "f"(w)
                         : "memory");
        }
        if (v1) {
            int g1 = batch[r1];
            float *p1 = pool + (size_t)g1 * DD;
#pragma unroll
            for (int c = 0; c < 16; c++) {
                float lo, hi, z, w;
                unpack2(acc1[2 * c], lo, hi);
                unpack2(acc1[2 * c + 1], z, w);
                lo = fmaxf(lo, 0.f); hi = fmaxf(hi, 0.f);
                z = fmaxf(z, 0.f);  w = fmaxf(w, 0.f);
                asm volatile("red.global.add.v4.f32 [%0], {%1, %2, %3, %4};"
                             :: "l"(p1 + c * 4), "f"(lo), "f"(hi), "f"(z), "f"(w)
                             : "memory");
            }
        }
    }
}

// y = relu(pool @ W1 + b1) @ W2 + b2 ; one warp per graph, 4 graphs per block.
__global__ void head_kernel(const float *__restrict__ pool,
                            const float *__restrict__ W1,
                            const float *__restrict__ b1,
                            const float *__restrict__ W2,
                            const float *__restrict__ b2,
                            float *__restrict__ out) {
    __shared__ float st[4][DD];
    int w = threadIdx.x >> 5;
    int lane = threadIdx.x & 31;
    int g = blockIdx.x * 4 + w;

    float acc0 = b1[lane];
    float acc1 = b1[lane + 32];
#pragma unroll 4
    for (int k = 0; k < DD; k++) {
        float pv = pool[g * DD + k];
        acc0 += pv * W1[k * DD + lane];
        acc1 += pv * W1[k * DD + lane + 32];
    }
    st[w][lane] = fmaxf(acc0, 0.f);
    st[w][lane + 32] = fmaxf(acc1, 0.f);
    __syncwarp();

    if (lane < OUTD) {
        float acc = b2[lane];
#pragma unroll 4
        for (int k = 0; k < DD; k++) acc += st[w][k] * W2[k * OUTD + lane];
        out[g * OUTD + lane] = acc;
    }
}

extern "C" void kernel_launch(void *const *d_in, const int *in_sizes, int n_in,
                              void *d_out, int out_size) {
    const float *x     = (const float *)d_in[0];
    const int   *ei    = (const int *)d_in[1];
    const int   *batch = (const int *)d_in[2];
    const float *Wrel  = (const float *)d_in[3];
    const float *brel  = (const float *)d_in[4];
    const float *Wroot = (const float *)d_in[5];
    const float *W1    = (const float *)d_in[6];
    const float *b1    = (const float *)d_in[7];
    const float *W2    = (const float *)d_in[8];
    const float *b2    = (const float *)d_in[9];

    int nE = in_sizes[1] / 2;
    int nN = in_sizes[0] / DD;
    const int *src = ei;
    const int *dst = ei + nE;

    float *bufA, *bufB, *agg, *pool;
    int *rowStart, *cursor, *bsum, *csrSrc;
    cudaGetSymbolAddress((void **)&bufA, g_bufA);
    cudaGetSymbolAddress((void **)&bufB, g_bufB);
    cudaGetSymbolAddress((void **)&agg, g_agg);
    cudaGetSymbolAddress((void **)&pool, g_pool);
    cudaGetSymbolAddress((void **)&rowStart, g_rowStart);
    cudaGetSymbolAddress((void **)&cursor, g_cursor);
    cudaGetSymbolAddress((void **)&bsum, g_bsum);
    cudaGetSymbolAddress((void **)&csrSrc, g_csrSrc);

    // ---- pool zero (independent; do it first) ----
    int poolN4 = NG * 16;
    zero_kernel<<<(poolN4 + 255) / 256, 256>>>((float4 *)pool, poolN4);

    // ---- CSR build (dst -> srcs), once per call ----
    int nb = (nN + SCAN_B - 1) / SCAN_B;
    zero_int_kernel<<<(nN + 511) / 512, 512>>>(rowStart, nN);
    hist_kernel<<<(nE + 511) / 512, 512>>>(dst, rowStart, nE);
    scan1_kernel<<<nb, SCAN_B>>>(rowStart, rowStart, bsum, nN);
    scan2_kernel<<<1, 256>>>(bsum, nb);
    scan3_kernel<<<(nN + 511) / 512, 512>>>(rowStart, bsum, cursor, nN, nE);
    fill_kernel<<<(nE + 511) / 512, 512>>>(src, dst, cursor, csrSrc, nE);

    const float *hcur = x;
    float *houts[NL] = {bufA, bufB, bufA, bufB};

    int gatherThreads = nN * 16;
    int nTiles = (nN + 255) / 256;
    for (int l = 0; l < NL; l++) {
        int isLast = (l == NL - 1);
        gather_kernel<<<(gatherThreads + 255) / 256, 256>>>(
            (const float4 *)hcur, rowStart, csrSrc, (float4 *)agg, nN);
        layer_kernel<<<nTiles, 128>>>(
            (const float4 *)agg, (const float4 *)hcur,
            Wrel + (size_t)l * DD * DD, Wroot + (size_t)l * DD * DD,
            brel + (size_t)l * DD, (float4 *)houts[l],
            batch, pool, nN, isLast);
        hcur = houts[l];
    }

    head_kernel<<<NG / 4, 128>>>(pool, W1, b1, W2, b2, (float *)d_out);
}